// round 1
// baseline (speedup 1.0000x reference)
#include <cuda_runtime.h>

#define KDIM 512
#define S_N 50000
#define EN 6
#define NEG 0.2f
#define NE3 150000

// ---------------- scratch (static __device__, no allocation) ----------------
__device__ float g_wa[4][2][KDIM];      // W_g @ a_src / a_dst
__device__ float g_he[4][EN][KDIM];     // exer_emb @ W_g
__device__ float g_ase[4][EN];          // h_e . a_src
__device__ float g_ade[4][EN];          // h_e . a_dst
__device__ float g_as2[S_N], g_ad2[S_N], g_as3[S_N];
__device__ float g_as0[KDIM], g_ad0[KDIM], g_as1[KDIM];
__device__ unsigned g_m1u[EN], g_m3u[EN];
__device__ float g_den1[EN], g_den3[EN];
__device__ float g_agg1[EN*KDIM], g_agg3[EN*KDIM];
__device__ float g_B[EN*KDIM], g_C[EN*KDIM];

__device__ __forceinline__ float lrelu(float x){ return x > 0.f ? x : NEG*x; }
__device__ __forceinline__ unsigned f2u(float f){
    unsigned u = __float_as_uint(f);
    return (u & 0x80000000u) ? ~u : (u | 0x80000000u);
}
__device__ __forceinline__ float u2f(unsigned u){
    return __uint_as_float((u & 0x80000000u) ? (u ^ 0x80000000u) : ~u);
}

// ---------------- K1: wa vectors + h_e rows + as_e/ad_e ----------------
__global__ void k_pre(const float* __restrict__ Wg, const float* __restrict__ a_src,
                      const float* __restrict__ a_dst, const float* __restrict__ exer){
    __shared__ float sv[KDIM];
    __shared__ float red[KDIM];
    int b = blockIdx.x, tid = threadIdx.x;
    if (b < 8) {
        int g = b >> 1, w = b & 1;
        const float* a = (w ? a_dst : a_src) + g*KDIM;
        sv[tid] = a[tid];
        __syncthreads();
        int lane = tid & 31, warp = tid >> 5;
        const float* Wb = Wg + (size_t)g*KDIM*KDIM;
        for (int r = warp; r < KDIM; r += 16) {
            float s = 0.f;
            for (int c = lane; c < KDIM; c += 32) s += Wb[r*KDIM + c] * sv[c];
            for (int o = 16; o; o >>= 1) s += __shfl_down_sync(0xffffffffu, s, o);
            if (lane == 0) g_wa[g][w][r] = s;
        }
    } else {
        int t = b - 8, g = t / EN, j = t % EN;
        sv[tid] = exer[j*KDIM + tid];
        __syncthreads();
        const float* Wb = Wg + (size_t)g*KDIM*KDIM;
        float acc = 0.f;
        for (int i = 0; i < KDIM; i++) acc += sv[i] * Wb[i*KDIM + tid];
        g_he[g][j][tid] = acc;
        red[tid] = acc * a_src[g*KDIM + tid];
        __syncthreads();
        for (int o = 256; o; o >>= 1){ if (tid < o) red[tid] += red[tid+o]; __syncthreads(); }
        if (tid == 0) g_ase[g][j] = red[0];
        __syncthreads();
        red[tid] = acc * a_dst[g*KDIM + tid];
        __syncthreads();
        for (int o = 256; o; o >>= 1){ if (tid < o) red[tid] += red[tid+o]; __syncthreads(); }
        if (tid == 0) g_ade[g][j] = red[0];
    }
}

// ---------------- K1c: inits (self-loop maxima, zero accumulators) ----------------
__global__ void k_init(){
    int tid = threadIdx.x;
    if (tid < EN) {
        g_m1u[tid] = f2u(lrelu(g_ase[1][tid] + g_ade[1][tid]));
        g_m3u[tid] = f2u(lrelu(g_ase[3][tid] + g_ade[3][tid]));
        g_den1[tid] = 0.f; g_den3[tid] = 0.f;
    }
    for (int i = tid; i < EN*KDIM; i += blockDim.x){ g_agg1[i] = 0.f; g_agg3[i] = 0.f; }
}

// ---------------- per-row 3-way matvec (attention logit scalars) ----------------
__global__ void k_matvec3(const float* __restrict__ X, int M, int mode){
    __shared__ float s0[KDIM], s1[KDIM], s2[KDIM];
    int tid = threadIdx.x;
    const float* w0 = mode ? g_wa[0][0] : g_wa[2][0];
    const float* w1 = mode ? g_wa[0][1] : g_wa[2][1];
    const float* w2 = mode ? g_wa[1][0] : g_wa[3][0];
    for (int i = tid; i < KDIM; i += 256){ s0[i]=w0[i]; s1[i]=w1[i]; s2[i]=w2[i]; }
    __syncthreads();
    int warp = tid >> 5, lane = tid & 31;
    int row = blockIdx.x*8 + warp;
    if (row >= M) return;
    float a0=0.f, a1=0.f, a2=0.f;
    const float* xr = X + (size_t)row*KDIM;
    for (int c = lane; c < KDIM; c += 32){
        float v = xr[c]; a0 += v*s0[c]; a1 += v*s1[c]; a2 += v*s2[c];
    }
    for (int o = 16; o; o >>= 1){
        a0 += __shfl_down_sync(0xffffffffu, a0, o);
        a1 += __shfl_down_sync(0xffffffffu, a1, o);
        a2 += __shfl_down_sync(0xffffffffu, a2, o);
    }
    if (lane == 0){
        if (mode){ g_as0[row]=a0; g_ad0[row]=a1; g_as1[row]=a2; }
        else     { g_as2[row]=a0; g_ad2[row]=a1; g_as3[row]=a2; }
    }
}

// ---------------- GAT1: max + den over 2048 edges, single block ----------------
__global__ void k_gat1(const int* __restrict__ ek){
    __shared__ unsigned sm[EN];
    __shared__ float sden[EN];
    int tid = threadIdx.x;
    if (tid < EN){ sm[tid] = g_m1u[tid]; sden[tid] = 0.f; }
    __syncthreads();
    for (int t = tid; t < 2048; t += 512){
        int k = ek[t] - EN, d = ek[2048 + t];
        atomicMax(&sm[d], f2u(lrelu(g_as1[k] + g_ade[1][d])));
    }
    __syncthreads();
    for (int t = tid; t < 2048; t += 512){
        int k = ek[t] - EN, d = ek[2048 + t];
        float e = lrelu(g_as1[k] + g_ade[1][d]);
        atomicAdd(&sden[d], expf(e - u2f(sm[d])));
    }
    if (tid < EN) atomicAdd(&sden[tid], expf(lrelu(g_ase[1][tid] + g_ade[1][tid]) - u2f(sm[tid])));
    __syncthreads();
    if (tid < EN){ g_m1u[tid] = sm[tid]; g_den1[tid] = sden[tid]; }
}

// ---------------- GAT1: weighted aggregation of kn rows ----------------
__global__ void k_agg1(const int* __restrict__ ek, const float* __restrict__ kn){
    __shared__ float sagg[EN][KDIM];
    __shared__ float sal[256];
    __shared__ int sd[256], ss[256];
    int tid = threadIdx.x;
    for (int i = tid; i < EN*KDIM; i += 512) ((float*)sagg)[i] = 0.f;
    int t0 = blockIdx.x*256;
    if (tid < 256){
        int t = t0 + tid;
        int k = ek[t] - EN, d = ek[2048 + t];
        float e = lrelu(g_as1[k] + g_ade[1][d]);
        sal[tid] = expf(e - u2f(g_m1u[d])) / g_den1[d];
        sd[tid] = d; ss[tid] = k;
    }
    __syncthreads();
    for (int el = 0; el < 256; el++)
        sagg[sd[el]][tid] += sal[el] * kn[(size_t)ss[el]*KDIM + tid];
    __syncthreads();
    for (int i = tid; i < EN*KDIM; i += 512) atomicAdd(&g_agg1[i], ((float*)sagg)[i]);
}

// ---------------- GAT3: segment max over 150k edges ----------------
__global__ void k_gat3_max(const int* __restrict__ eu, int nE){
    __shared__ unsigned sm[EN];
    int tid = threadIdx.x;
    if (tid < EN) sm[tid] = 0u;
    __syncthreads();
    int t = blockIdx.x*blockDim.x + tid;
    if (t < nE){
        int s = eu[t] - EN, d = eu[nE + t];
        atomicMax(&sm[d], f2u(lrelu(g_as3[s] + g_ade[3][d])));
    }
    __syncthreads();
    if (tid < EN && sm[tid]) atomicMax(&g_m3u[tid], sm[tid]);
}

// ---------------- GAT3: segment denominator ----------------
__global__ void k_gat3_den(const int* __restrict__ eu, int nE){
    __shared__ float sden[EN];
    int tid = threadIdx.x;
    if (tid < EN) sden[tid] = 0.f;
    __syncthreads();
    int t = blockIdx.x*blockDim.x + tid;
    if (t < nE){
        int s = eu[t] - EN, d = eu[nE + t];
        float e = lrelu(g_as3[s] + g_ade[3][d]);
        atomicAdd(&sden[d], expf(e - u2f(g_m3u[d])));
    }
    __syncthreads();
    if (tid < EN){
        float v = sden[tid];
        if (blockIdx.x == 0)
            v += expf(lrelu(g_ase[3][tid] + g_ade[3][tid]) - u2f(g_m3u[tid]));
        if (v != 0.f) atomicAdd(&g_den3[tid], v);
    }
}

// ---------------- GAT3: weighted aggregation of student rows ----------------
__global__ void k_gat3_agg(const int* __restrict__ eu, const float* __restrict__ X,
                           int nS, int nE){
    __shared__ float sagg[EN][KDIM];
    __shared__ float sal[192];
    __shared__ int sd[192];
    int tid = threadIdx.x;
    for (int i = tid; i < EN*KDIM; i += 256) ((float*)sagg)[i] = 0.f;
    int base = blockIdx.x*64;
    int nst = min(64, nS - base);
    if (tid < 3*nst){
        int t = base*3 + tid;
        int s = eu[t] - EN, d = eu[nE + t];
        float e = lrelu(g_as3[s] + g_ade[3][d]);
        sal[tid] = expf(e - u2f(g_m3u[d])) / g_den3[d];
        sd[tid] = d;
    }
    __syncthreads();
    for (int sl = 0; sl < nst; sl++){
        int s = base + sl;
        float v0 = X[(size_t)s*KDIM + tid];
        float v1 = X[(size_t)s*KDIM + 256 + tid];
        #pragma unroll
        for (int j = 0; j < 3; j++){
            int d = sd[3*sl + j]; float al = sal[3*sl + j];
            sagg[d][tid]       += al*v0;
            sagg[d][256 + tid] += al*v1;
        }
    }
    __syncthreads();
    for (int i = tid; i < EN*KDIM; i += 256) atomicAdd(&g_agg3[i], ((float*)sagg)[i]);
}

// ---------------- B = agg1@W1 + b1 ; C = agg3@W3 + b3 ----------------
__global__ void k_bc(const float* __restrict__ Wg, const float* __restrict__ bg,
                     const float* __restrict__ exer){
    __shared__ float srow[KDIM];
    int r = blockIdx.x, tid = threadIdx.x;
    int isB = (r < EN) ? 1 : 0;
    int e = isB ? r : r - EN;
    int g = isB ? 1 : 3;
    float m   = u2f(isB ? g_m1u[e] : g_m3u[e]);
    float den = isB ? g_den1[e] : g_den3[e];
    float aself = expf(lrelu(g_ase[g][e] + g_ade[g][e]) - m) / den;
    const float* agg = isB ? g_agg1 : g_agg3;
    srow[tid] = agg[e*KDIM + tid] + aself * exer[e*KDIM + tid];
    __syncthreads();
    const float* Wb = Wg + (size_t)g*KDIM*KDIM;
    float acc = bg[g*KDIM + tid];
    for (int i = 0; i < KDIM; i++) acc += srow[i] * Wb[i*KDIM + tid];
    float* dst = isB ? g_B : g_C;
    dst[e*KDIM + tid] = acc;
}

// ---------------- exer_out: two-logit softmax combine ----------------
__global__ void k_exer(const float* __restrict__ exer, const float* __restrict__ aw,
                       const float* __restrict__ ab, float* __restrict__ outE){
    __shared__ float red[KDIM];
    int tid = threadIdx.x;
    for (int e = 0; e < EN; e++){
        float xv = exer[e*KDIM + tid];
        float bv = g_B[e*KDIM + tid];
        float cv = g_C[e*KDIM + tid];
        red[tid] = xv*aw[1024 + tid] + bv*aw[1024 + KDIM + tid];
        __syncthreads();
        for (int o = 256; o; o >>= 1){ if (tid < o) red[tid] += red[tid+o]; __syncthreads(); }
        float s1 = red[0] + ab[1];
        __syncthreads();
        red[tid] = xv*aw[2048 + tid] + cv*aw[2048 + KDIM + tid];
        __syncthreads();
        for (int o = 256; o; o >>= 1){ if (tid < o) red[tid] += red[tid+o]; __syncthreads(); }
        float s2 = red[0] + ab[2];
        __syncthreads();
        float mx = fmaxf(s1, s2);
        float e1 = expf(s1 - mx), e2 = expf(s2 - mx);
        float inv = 1.f / (e1 + e2);
        outE[e*KDIM + tid] = xv + (e1*inv)*bv + (e2*inv)*cv;
    }
}

// ---------------- main GEMM with fused GAT epilogue ----------------
// out[row] = x[row] + b + alpha_self*(x[row]@W) + sum_j alpha_j*h_e[src_j]
// gsel 0: GAT0 (kn rows, deg=4);  gsel 2: GAT2 (student rows, deg=3)
__global__ void __launch_bounds__(256) k_gemm_gat(
    const float* __restrict__ A, const float* __restrict__ W,
    const float* __restrict__ b, const int* __restrict__ esrc,
    int deg, int M, float* __restrict__ out, int gsel)
{
    __shared__ float As[8][128];
    __shared__ float Bs[8][128];
    __shared__ float he_s[EN][128];
    __shared__ float b_s[128];
    __shared__ float ase_s[EN];
    int tid = threadIdx.x;
    int tx = tid & 15, ty = tid >> 4;
    int rowBase = blockIdx.y*128, colBase = blockIdx.x*128;

    const float* he    = &g_he[gsel][0][0];
    const float* as_e  = g_ase[gsel];
    const float* as_row = gsel ? g_as2 : g_as0;
    const float* ad_row = gsel ? g_ad2 : g_ad0;

    if (tid < 128) b_s[tid] = b[colBase + tid];
    if (tid >= 128 && tid < 128 + EN) ase_s[tid - 128] = as_e[tid - 128];
    for (int i = tid; i < EN*128; i += 256){
        int j = i >> 7, c = i & 127;
        he_s[j][c] = he[j*KDIM + colBase + c];
    }

    int aRow = tid >> 1, aCol = (tid & 1)*4;
    int bRow = tid >> 5, bCol = (tid & 31)*4;
    int gr = rowBase + aRow; if (gr > M-1) gr = M-1;
    const float* Aptr = A + (size_t)gr*KDIM + aCol;
    const float* Wptr = W + (size_t)bRow*KDIM + colBase + bCol;

    float acc[8][8];
    #pragma unroll
    for (int i = 0; i < 8; i++)
        #pragma unroll
        for (int j = 0; j < 8; j++) acc[i][j] = 0.f;

    for (int k0 = 0; k0 < KDIM; k0 += 8){
        float4 av = *(const float4*)(Aptr + k0);
        float4 wv = *(const float4*)(Wptr + (size_t)k0*KDIM);
        __syncthreads();
        As[aCol+0][aRow] = av.x; As[aCol+1][aRow] = av.y;
        As[aCol+2][aRow] = av.z; As[aCol+3][aRow] = av.w;
        *(float4*)&Bs[bRow][bCol] = wv;
        __syncthreads();
        #pragma unroll
        for (int kk = 0; kk < 8; kk++){
            float4 a0 = *(const float4*)&As[kk][ty*8];
            float4 a1 = *(const float4*)&As[kk][ty*8 + 4];
            float4 b0 = *(const float4*)&Bs[kk][tx*8];
            float4 b1 = *(const float4*)&Bs[kk][tx*8 + 4];
            float ar[8] = {a0.x,a0.y,a0.z,a0.w,a1.x,a1.y,a1.z,a1.w};
            float br[8] = {b0.x,b0.y,b0.z,b0.w,b1.x,b1.y,b1.z,b1.w};
            #pragma unroll
            for (int i = 0; i < 8; i++)
                #pragma unroll
                for (int j = 0; j < 8; j++)
                    acc[i][j] += ar[i]*br[j];
        }
    }

    #pragma unroll
    for (int i = 0; i < 8; i++){
        int row = rowBase + ty*8 + i;
        if (row >= M) break;
        float asv = as_row[row], adv = ad_row[row];
        float eself = lrelu(asv + adv);
        float mx = eself;
        int srcs[4]; float ev[4];
        #pragma unroll 4
        for (int j = 0; j < deg; j++){
            int s = esrc[row*deg + j];
            srcs[j] = s;
            float e = lrelu(ase_s[s] + adv);
            ev[j] = e; mx = fmaxf(mx, e);
        }
        float aself = expf(eself - mx);
        float se = aself;
        float al[4];
        #pragma unroll 4
        for (int j = 0; j < deg; j++){ al[j] = expf(ev[j] - mx); se += al[j]; }
        float inv = 1.f / se;
        aself *= inv;
        #pragma unroll 4
        for (int j = 0; j < deg; j++) al[j] *= inv;

        const float* xr = A + (size_t)row*KDIM + colBase;
        float* orow = out + (size_t)row*KDIM + colBase;
        #pragma unroll
        for (int jj = 0; jj < 8; jj++){
            int c = tx*8 + jj;
            float v = xr[c] + b_s[c] + aself*acc[i][jj];
            #pragma unroll 4
            for (int j = 0; j < deg; j++) v += al[j]*he_s[srcs[j]][c];
            orow[c] = v;
        }
    }
}

// ---------------- launcher ----------------
extern "C" void kernel_launch(void* const* d_in, const int* in_sizes, int n_in,
                              void* d_out, int out_size){
    const float* kn   = (const float*)d_in[0];
    const float* exer = (const float*)d_in[1];
    const float* stu  = (const float*)d_in[2];
    const float* Wg   = (const float*)d_in[3];
    const float* a_s  = (const float*)d_in[4];
    const float* a_d  = (const float*)d_in[5];
    const float* bg   = (const float*)d_in[6];
    const float* aw   = (const float*)d_in[7];
    const float* ab   = (const float*)d_in[8];
    const int* eke    = (const int*)d_in[9];
    const int* eek    = (const int*)d_in[10];
    const int* eue    = (const int*)d_in[11];
    const int* eeu    = (const int*)d_in[12];
    (void)in_sizes; (void)n_in; (void)out_size;

    float* out    = (float*)d_out;
    float* out_kn = out;
    float* out_ex = out + KDIM*KDIM;
    float* out_st = out + KDIM*KDIM + EN*KDIM;

    k_pre<<<32, 512>>>(Wg, a_s, a_d, exer);
    k_init<<<1, 512>>>();
    k_matvec3<<<(S_N + 7)/8, 256>>>(stu, S_N, 0);
    k_matvec3<<<(KDIM + 7)/8, 256>>>(kn, KDIM, 1);

    // GAT1 -> agg1
    k_gat1<<<1, 512>>>(eek);
    k_agg1<<<8, 512>>>(eek, kn);

    // GAT3 -> agg3
    k_gat3_max<<<(NE3 + 511)/512, 512>>>(eeu, NE3);
    k_gat3_den<<<(NE3 + 511)/512, 512>>>(eeu, NE3);
    k_gat3_agg<<<(S_N + 63)/64, 256>>>(eeu, stu, S_N, NE3);

    // B, C small GEMMs then exer_out
    k_bc<<<12, 512>>>(Wg, bg, exer);
    k_exer<<<1, 512>>>(exer, aw, ab, out_ex);

    // GAT0: kn_out (M=512, deg=4)
    {
        dim3 grid(4, 4);
        k_gemm_gat<<<grid, 256>>>(kn, Wg, bg, eke, 4, KDIM, out_kn, 0);
    }
    // GAT2: stu_out (M=50000, deg=3)
    {
        dim3 grid(4, (S_N + 127)/128);
        k_gemm_gat<<<grid, 256>>>(stu, Wg + 2*KDIM*KDIM, bg + 2*KDIM,
                                  eue, 3, S_N, out_st, 2);
    }
}

// round 3
// speedup vs baseline: 1.7111x; 1.7111x over previous
#include <cuda_runtime.h>
#include <cuda_bf16.h>
#include <cstdint>

#define KDIM 512
#define S_N 50000
#define EN 6
#define NEG 0.2f
#define NE3 150000

// ---------------- scratch (static __device__, no allocation) ----------------
__device__ float g_wa[4][2][KDIM];      // W_g @ a_src / a_dst
__device__ float g_he[4][EN][KDIM];     // exer_emb @ W_g
__device__ float g_ase[4][EN];          // h_e . a_src
__device__ float g_ade[4][EN];          // h_e . a_dst
__device__ float g_as2[S_N], g_ad2[S_N], g_as3[S_N];
__device__ float g_as0[KDIM], g_ad0[KDIM], g_as1[KDIM];
__device__ unsigned g_m1u[EN], g_m3u[EN];
__device__ float g_den1[EN], g_den3[EN];
__device__ float g_agg1[EN*KDIM], g_agg3[EN*KDIM];
__device__ float g_B[EN*KDIM], g_C[EN*KDIM];

// bf16 split operands for the tensor-core student GEMM
__device__ __nv_bfloat16 g_Ahi[(size_t)S_N*KDIM];
__device__ __nv_bfloat16 g_Alo[(size_t)S_N*KDIM];
__device__ __nv_bfloat16 g_Bhi[KDIM*KDIM];   // W2^T split hi: [n][k]
__device__ __nv_bfloat16 g_Blo[KDIM*KDIM];   // W2^T split lo: [n][k]

__device__ __forceinline__ float lrelu(float x){ return x > 0.f ? x : NEG*x; }
__device__ __forceinline__ unsigned f2u(float f){
    unsigned u = __float_as_uint(f);
    return (u & 0x80000000u) ? ~u : (u | 0x80000000u);
}
__device__ __forceinline__ float u2f(unsigned u){
    return __uint_as_float((u & 0x80000000u) ? (u ^ 0x80000000u) : ~u);
}

// ---------------- PTX helpers (all legal on plain compute_103) ----------------
__device__ __forceinline__ uint32_t smem_u32(const void* p){
    uint32_t a;
    asm("{ .reg .u64 t; cvta.to.shared.u64 t, %1; cvt.u32.u64 %0, t; }" : "=r"(a) : "l"(p));
    return a;
}
__device__ __forceinline__ void cpa16(uint32_t s, const void* g){
    asm volatile("cp.async.cg.shared.global [%0], [%1], 16;" :: "r"(s), "l"(g));
}
#define CPA_COMMIT() asm volatile("cp.async.commit_group;" ::: "memory")
#define CPA_WAIT(n)  asm volatile("cp.async.wait_group %0;" :: "n"(n) : "memory")

__device__ __forceinline__ void ldsm4(uint32_t& r0, uint32_t& r1, uint32_t& r2, uint32_t& r3,
                                      uint32_t addr){
    asm volatile("ldmatrix.sync.aligned.m8n8.x4.shared.b16 {%0,%1,%2,%3}, [%4];"
                 : "=r"(r0), "=r"(r1), "=r"(r2), "=r"(r3) : "r"(addr));
}
__device__ __forceinline__ void mma16816(float* c, const uint32_t* a, const uint32_t* b){
    asm volatile(
        "mma.sync.aligned.m16n8k16.row.col.f32.bf16.bf16.f32 "
        "{%0,%1,%2,%3}, {%4,%5,%6,%7}, {%8,%9}, {%0,%1,%2,%3};"
        : "+f"(c[0]), "+f"(c[1]), "+f"(c[2]), "+f"(c[3])
        : "r"(a[0]), "r"(a[1]), "r"(a[2]), "r"(a[3]), "r"(b[0]), "r"(b[1]));
}

// ---------------- K1: wa vectors + h_e rows + as_e/ad_e ----------------
__global__ void k_pre(const float* __restrict__ Wg, const float* __restrict__ a_src,
                      const float* __restrict__ a_dst, const float* __restrict__ exer){
    __shared__ float sv[KDIM];
    __shared__ float red[KDIM];
    int b = blockIdx.x, tid = threadIdx.x;
    if (b < 8) {
        int g = b >> 1, w = b & 1;
        const float* a = (w ? a_dst : a_src) + g*KDIM;
        sv[tid] = a[tid];
        __syncthreads();
        int lane = tid & 31, warp = tid >> 5;
        const float* Wb = Wg + (size_t)g*KDIM*KDIM;
        for (int r = warp; r < KDIM; r += 16) {
            float s = 0.f;
            for (int c = lane; c < KDIM; c += 32) s += Wb[r*KDIM + c] * sv[c];
            for (int o = 16; o; o >>= 1) s += __shfl_down_sync(0xffffffffu, s, o);
            if (lane == 0) g_wa[g][w][r] = s;
        }
    } else {
        int t = b - 8, g = t / EN, j = t % EN;
        sv[tid] = exer[j*KDIM + tid];
        __syncthreads();
        const float* Wb = Wg + (size_t)g*KDIM*KDIM;
        float acc = 0.f;
        for (int i = 0; i < KDIM; i++) acc += sv[i] * Wb[i*KDIM + tid];
        g_he[g][j][tid] = acc;
        red[tid] = acc * a_src[g*KDIM + tid];
        __syncthreads();
        for (int o = 256; o; o >>= 1){ if (tid < o) red[tid] += red[tid+o]; __syncthreads(); }
        if (tid == 0) g_ase[g][j] = red[0];
        __syncthreads();
        red[tid] = acc * a_dst[g*KDIM + tid];
        __syncthreads();
        for (int o = 256; o; o >>= 1){ if (tid < o) red[tid] += red[tid+o]; __syncthreads(); }
        if (tid == 0) g_ade[g][j] = red[0];
    }
}

// ---------------- inits ----------------
__global__ void k_init(){
    int tid = threadIdx.x;
    if (tid < EN) {
        g_m1u[tid] = f2u(lrelu(g_ase[1][tid] + g_ade[1][tid]));
        g_m3u[tid] = f2u(lrelu(g_ase[3][tid] + g_ade[3][tid]));
        g_den1[tid] = 0.f; g_den3[tid] = 0.f;
    }
    for (int i = tid; i < EN*KDIM; i += blockDim.x){ g_agg1[i] = 0.f; g_agg3[i] = 0.f; }
}

// ---------------- split W2^T into bf16 hi/lo ----------------
__global__ void k_split_W(const float* __restrict__ Wg){
    int n = blockIdx.x;
    const float* W2 = Wg + 2*KDIM*KDIM;
    for (int k = threadIdx.x; k < KDIM; k += 256){
        float v = W2[k*KDIM + n];
        __nv_bfloat16 h = __float2bfloat16(v);
        g_Bhi[n*KDIM + k] = h;
        g_Blo[n*KDIM + k] = __float2bfloat16(v - __bfloat162float(h));
    }
}

// ---------------- fused: split students into bf16 hi/lo + 3-way matvec ----------------
__global__ void k_split_mv(const float* __restrict__ stu){
    __shared__ float s0[KDIM], s1[KDIM], s2[KDIM];
    int tid = threadIdx.x;
    for (int i = tid; i < KDIM; i += 256){
        s0[i] = g_wa[2][0][i]; s1[i] = g_wa[2][1][i]; s2[i] = g_wa[3][0][i];
    }
    __syncthreads();
    int warp = tid >> 5, lane = tid & 31;
    int row = blockIdx.x*8 + warp;
    if (row >= S_N) return;
    const float4* xr = (const float4*)(stu + (size_t)row*KDIM);
    __nv_bfloat162* hi2 = (__nv_bfloat162*)(g_Ahi + (size_t)row*KDIM);
    __nv_bfloat162* lo2 = (__nv_bfloat162*)(g_Alo + (size_t)row*KDIM);
    float a0 = 0.f, a1 = 0.f, a2 = 0.f;
    #pragma unroll
    for (int i = 0; i < 4; i++){
        int q = lane + 32*i;
        float4 f = xr[q];
        int c = 4*q;
        a0 += f.x*s0[c] + f.y*s0[c+1] + f.z*s0[c+2] + f.w*s0[c+3];
        a1 += f.x*s1[c] + f.y*s1[c+1] + f.z*s1[c+2] + f.w*s1[c+3];
        a2 += f.x*s2[c] + f.y*s2[c+1] + f.z*s2[c+2] + f.w*s2[c+3];
        __nv_bfloat16 hx = __float2bfloat16(f.x), hy = __float2bfloat16(f.y);
        __nv_bfloat16 hz = __float2bfloat16(f.z), hw = __float2bfloat16(f.w);
        hi2[2*q]   = __halves2bfloat162(hx, hy);
        hi2[2*q+1] = __halves2bfloat162(hz, hw);
        lo2[2*q]   = __halves2bfloat162(__float2bfloat16(f.x - __bfloat162float(hx)),
                                        __float2bfloat16(f.y - __bfloat162float(hy)));
        lo2[2*q+1] = __halves2bfloat162(__float2bfloat16(f.z - __bfloat162float(hz)),
                                        __float2bfloat16(f.w - __bfloat162float(hw)));
    }
    for (int o = 16; o; o >>= 1){
        a0 += __shfl_down_sync(0xffffffffu, a0, o);
        a1 += __shfl_down_sync(0xffffffffu, a1, o);
        a2 += __shfl_down_sync(0xffffffffu, a2, o);
    }
    if (lane == 0){ g_as2[row] = a0; g_ad2[row] = a1; g_as3[row] = a2; }
}

// ---------------- kn 3-way matvec ----------------
__global__ void k_matvec3(const float* __restrict__ X, int M){
    __shared__ float s0[KDIM], s1[KDIM], s2[KDIM];
    int tid = threadIdx.x;
    for (int i = tid; i < KDIM; i += 256){
        s0[i] = g_wa[0][0][i]; s1[i] = g_wa[0][1][i]; s2[i] = g_wa[1][0][i];
    }
    __syncthreads();
    int warp = tid >> 5, lane = tid & 31;
    int row = blockIdx.x*8 + warp;
    if (row >= M) return;
    float a0 = 0.f, a1 = 0.f, a2 = 0.f;
    const float* xr = X + (size_t)row*KDIM;
    for (int c = lane; c < KDIM; c += 32){
        float v = xr[c]; a0 += v*s0[c]; a1 += v*s1[c]; a2 += v*s2[c];
    }
    for (int o = 16; o; o >>= 1){
        a0 += __shfl_down_sync(0xffffffffu, a0, o);
        a1 += __shfl_down_sync(0xffffffffu, a1, o);
        a2 += __shfl_down_sync(0xffffffffu, a2, o);
    }
    if (lane == 0){ g_as0[row] = a0; g_ad0[row] = a1; g_as1[row] = a2; }
}

// ---------------- GAT1: max + den over 2048 edges ----------------
__global__ void k_gat1(const int* __restrict__ ek){
    __shared__ unsigned sm[EN];
    __shared__ float sden[EN];
    int tid = threadIdx.x;
    if (tid < EN){ sm[tid] = g_m1u[tid]; sden[tid] = 0.f; }
    __syncthreads();
    for (int t = tid; t < 2048; t += 512){
        int k = ek[t] - EN, d = ek[2048 + t];
        atomicMax(&sm[d], f2u(lrelu(g_as1[k] + g_ade[1][d])));
    }
    __syncthreads();
    for (int t = tid; t < 2048; t += 512){
        int k = ek[t] - EN, d = ek[2048 + t];
        float e = lrelu(g_as1[k] + g_ade[1][d]);
        atomicAdd(&sden[d], expf(e - u2f(sm[d])));
    }
    if (tid < EN) atomicAdd(&sden[tid], expf(lrelu(g_ase[1][tid] + g_ade[1][tid]) - u2f(sm[tid])));
    __syncthreads();
    if (tid < EN){ g_m1u[tid] = sm[tid]; g_den1[tid] = sden[tid]; }
}

// ---------------- GAT1 aggregation ----------------
__global__ void k_agg1(const int* __restrict__ ek, const float* __restrict__ kn){
    __shared__ float sagg[EN][KDIM];
    __shared__ float sal[256];
    __shared__ int sd[256], ss[256];
    int tid = threadIdx.x;
    for (int i = tid; i < EN*KDIM; i += 512) ((float*)sagg)[i] = 0.f;
    int t0 = blockIdx.x*256;
    if (tid < 256){
        int t = t0 + tid;
        int k = ek[t] - EN, d = ek[2048 + t];
        float e = lrelu(g_as1[k] + g_ade[1][d]);
        sal[tid] = expf(e - u2f(g_m1u[d])) / g_den1[d];
        sd[tid] = d; ss[tid] = k;
    }
    __syncthreads();
    for (int el = 0; el < 256; el++)
        sagg[sd[el]][tid] += sal[el] * kn[(size_t)ss[el]*KDIM + tid];
    __syncthreads();
    for (int i = tid; i < EN*KDIM; i += 512) atomicAdd(&g_agg1[i], ((float*)sagg)[i]);
}

// ---------------- GAT3 max / den ----------------
__global__ void k_gat3_max(const int* __restrict__ eu, int nE){
    __shared__ unsigned sm[EN];
    int tid = threadIdx.x;
    if (tid < EN) sm[tid] = 0u;
    __syncthreads();
    int t = blockIdx.x*blockDim.x + tid;
    if (t < nE){
        int s = eu[t] - EN, d = eu[nE + t];
        atomicMax(&sm[d], f2u(lrelu(g_as3[s] + g_ade[3][d])));
    }
    __syncthreads();
    if (tid < EN && sm[tid]) atomicMax(&g_m3u[tid], sm[tid]);
}

__global__ void k_gat3_den(const int* __restrict__ eu, int nE){
    __shared__ float sden[EN];
    int tid = threadIdx.x;
    if (tid < EN) sden[tid] = 0.f;
    __syncthreads();
    int t = blockIdx.x*blockDim.x + tid;
    if (t < nE){
        int s = eu[t] - EN, d = eu[nE + t];
        float e = lrelu(g_as3[s] + g_ade[3][d]);
        atomicAdd(&sden[d], expf(e - u2f(g_m3u[d])));
    }
    __syncthreads();
    if (tid < EN){
        float v = sden[tid];
        if (blockIdx.x == 0)
            v += expf(lrelu(g_ase[3][tid] + g_ade[3][tid]) - u2f(g_m3u[tid]));
        if (v != 0.f) atomicAdd(&g_den3[tid], v);
    }
}

// ---------------- GAT3 aggregation ----------------
__global__ void k_gat3_agg(const int* __restrict__ eu, const float* __restrict__ X,
                           int nS, int nE){
    __shared__ float sagg[EN][KDIM];
    __shared__ float sal[192];
    __shared__ int sd[192];
    int tid = threadIdx.x;
    for (int i = tid; i < EN*KDIM; i += 256) ((float*)sagg)[i] = 0.f;
    int base = blockIdx.x*64;
    int nst = min(64, nS - base);
    if (tid < 3*nst){
        int t = base*3 + tid;
        int s = eu[t] - EN, d = eu[nE + t];
        float e = lrelu(g_as3[s] + g_ade[3][d]);
        sal[tid] = expf(e - u2f(g_m3u[d])) / g_den3[d];
        sd[tid] = d;
    }
    __syncthreads();
    for (int sl = 0; sl < nst; sl++){
        int s = base + sl;
        float v0 = X[(size_t)s*KDIM + tid];
        float v1 = X[(size_t)s*KDIM + 256 + tid];
        #pragma unroll
        for (int j = 0; j < 3; j++){
            int d = sd[3*sl + j]; float al = sal[3*sl + j];
            sagg[d][tid]       += al*v0;
            sagg[d][256 + tid] += al*v1;
        }
    }
    __syncthreads();
    for (int i = tid; i < EN*KDIM; i += 256) atomicAdd(&g_agg3[i], ((float*)sagg)[i]);
}

// ---------------- B = agg1@W1+b1 ; C = agg3@W3+b3 ----------------
__global__ void k_bc(const float* __restrict__ Wg, const float* __restrict__ bg,
                     const float* __restrict__ exer){
    __shared__ float srow[KDIM];
    int r = blockIdx.x, tid = threadIdx.x;
    int isB = (r < EN) ? 1 : 0;
    int e = isB ? r : r - EN;
    int g = isB ? 1 : 3;
    float m   = u2f(isB ? g_m1u[e] : g_m3u[e]);
    float den = isB ? g_den1[e] : g_den3[e];
    float aself = expf(lrelu(g_ase[g][e] + g_ade[g][e]) - m) / den;
    const float* agg = isB ? g_agg1 : g_agg3;
    srow[tid] = agg[e*KDIM + tid] + aself * exer[e*KDIM + tid];
    __syncthreads();
    const float* Wb = Wg + (size_t)g*KDIM*KDIM;
    float acc = bg[g*KDIM + tid];
    for (int i = 0; i < KDIM; i++) acc += srow[i] * Wb[i*KDIM + tid];
    float* dst = isB ? g_B : g_C;
    dst[e*KDIM + tid] = acc;
}

// ---------------- exer_out ----------------
__global__ void k_exer(const float* __restrict__ exer, const float* __restrict__ aw,
                       const float* __restrict__ ab, float* __restrict__ outE){
    __shared__ float red[KDIM];
    int tid = threadIdx.x;
    for (int e = 0; e < EN; e++){
        float xv = exer[e*KDIM + tid];
        float bv = g_B[e*KDIM + tid];
        float cv = g_C[e*KDIM + tid];
        red[tid] = xv*aw[1024 + tid] + bv*aw[1024 + KDIM + tid];
        __syncthreads();
        for (int o = 256; o; o >>= 1){ if (tid < o) red[tid] += red[tid+o]; __syncthreads(); }
        float s1 = red[0] + ab[1];
        __syncthreads();
        red[tid] = xv*aw[2048 + tid] + cv*aw[2048 + KDIM + tid];
        __syncthreads();
        for (int o = 256; o; o >>= 1){ if (tid < o) red[tid] += red[tid+o]; __syncthreads(); }
        float s2 = red[0] + ab[2];
        __syncthreads();
        float mx = fmaxf(s1, s2);
        float e1 = expf(s1 - mx), e2 = expf(s2 - mx);
        float inv = 1.f / (e1 + e2);
        outE[e*KDIM + tid] = xv + (e1*inv)*bv + (e2*inv)*cv;
    }
}

// ---------------- kn SIMT GEMM with fused GAT epilogue (M=512 only) ----------------
__global__ void __launch_bounds__(256) k_gemm_gat(
    const float* __restrict__ A, const float* __restrict__ W,
    const float* __restrict__ b, const int* __restrict__ esrc,
    int M, float* __restrict__ out)
{
    __shared__ float As[8][128];
    __shared__ float Bs[8][128];
    __shared__ float he_s[EN][128];
    __shared__ float b_s[128];
    __shared__ float ase_s[EN];
    int tid = threadIdx.x;
    int tx = tid & 15, ty = tid >> 4;
    int rowBase = blockIdx.y*128, colBase = blockIdx.x*128;

    if (tid < 128) b_s[tid] = b[colBase + tid];
    if (tid >= 128 && tid < 128 + EN) ase_s[tid - 128] = g_ase[0][tid - 128];
    for (int i = tid; i < EN*128; i += 256){
        int j = i >> 7, c = i & 127;
        he_s[j][c] = g_he[0][j][colBase + c];
    }

    int aRow = tid >> 1, aCol = (tid & 1)*4;
    int bRow = tid >> 5, bCol = (tid & 31)*4;
    int gr = rowBase + aRow; if (gr > M-1) gr = M-1;
    const float* Aptr = A + (size_t)gr*KDIM + aCol;
    const float* Wptr = W + (size_t)bRow*KDIM + colBase + bCol;

    float acc[8][8];
    #pragma unroll
    for (int i = 0; i < 8; i++)
        #pragma unroll
        for (int j = 0; j < 8; j++) acc[i][j] = 0.f;

    for (int k0 = 0; k0 < KDIM; k0 += 8){
        float4 av = *(const float4*)(Aptr + k0);
        float4 wv = *(const float4*)(Wptr + (size_t)k0*KDIM);
        __syncthreads();
        As[aCol+0][aRow] = av.x; As[aCol+1][aRow] = av.y;
        As[aCol+2][aRow] = av.z; As[aCol+3][aRow] = av.w;
        *(float4*)&Bs[bRow][bCol] = wv;
        __syncthreads();
        #pragma unroll
        for (int kk = 0; kk < 8; kk++){
            float4 a0 = *(const float4*)&As[kk][ty*8];
            float4 a1 = *(const float4*)&As[kk][ty*8 + 4];
            float4 b0 = *(const float4*)&Bs[kk][tx*8];
            float4 b1 = *(const float4*)&Bs[kk][tx*8 + 4];
            float ar[8] = {a0.x,a0.y,a0.z,a0.w,a1.x,a1.y,a1.z,a1.w};
            float br[8] = {b0.x,b0.y,b0.z,b0.w,b1.x,b1.y,b1.z,b1.w};
            #pragma unroll
            for (int i = 0; i < 8; i++)
                #pragma unroll
                for (int j = 0; j < 8; j++)
                    acc[i][j] += ar[i]*br[j];
        }
    }

    #pragma unroll
    for (int i = 0; i < 8; i++){
        int row = rowBase + ty*8 + i;
        if (row >= M) break;
        float asv = g_as0[row], adv = g_ad0[row];
        float eself = lrelu(asv + adv);
        float mx = eself;
        int srcs[4]; float ev[4];
        #pragma unroll
        for (int j = 0; j < 4; j++){
            int s = esrc[row*4 + j];
            srcs[j] = s;
            float e = lrelu(ase_s[s] + adv);
            ev[j] = e; mx = fmaxf(mx, e);
        }
        float aself = expf(eself - mx);
        float se = aself;
        float al[4];
        #pragma unroll
        for (int j = 0; j < 4; j++){ al[j] = expf(ev[j] - mx); se += al[j]; }
        float inv = 1.f / se;
        aself *= inv;
        #pragma unroll
        for (int j = 0; j < 4; j++) al[j] *= inv;

        const float* xr = A + (size_t)row*KDIM + colBase;
        float* orow = out + (size_t)row*KDIM + colBase;
        #pragma unroll
        for (int jj = 0; jj < 8; jj++){
            int c = tx*8 + jj;
            float v = xr[c] + b_s[c] + aself*acc[i][jj];
            #pragma unroll
            for (int j = 0; j < 4; j++) v += al[j]*he_s[srcs[j]][c];
            orow[c] = v;
        }
    }
}

// ---------------- student GEMM: mma.sync bf16 3-split + fused GAT epilogue -------
// CTA tile 128x64, 8 warps of 32x32, K-chunk 32, 2-stage cp.async pipeline.
// smem per split-stage: A 128x(32+8pad)x2B = 10240B, B 64x40x2B = 5120B
#define A_STG 10240
#define B_STG 5120
#define STG   (2*A_STG + 2*B_STG)       // 30720
#define MMA_SMEM (2*STG)                // 61440

__global__ void __launch_bounds__(256, 2) k_gemm_mma(
    const float* __restrict__ stu, const int* __restrict__ esrc,
    const float* __restrict__ bg, float* __restrict__ out)
{
    extern __shared__ char dsm[];
    __shared__ float he_s[EN][64];
    __shared__ float b_s[64];
    __shared__ float ase_s[EN];

    const uint32_t sb = smem_u32(dsm);
    int tid = threadIdx.x, lane = tid & 31, wid = tid >> 5;
    int mBase = blockIdx.y * 128, nBase = blockIdx.x * 64;

    // stage epilogue constants (consumed after first __syncthreads)
    for (int i = tid; i < EN*64; i += 256)
        he_s[i >> 6][i & 63] = g_he[2][i >> 6][nBase + (i & 63)];
    if (tid < 64) b_s[tid] = bg[2*KDIM + nBase + tid];
    if (tid < EN) ase_s[tid] = g_ase[2][tid];

    const char* gAh = (const char*)g_Ahi;
    const char* gAl = (const char*)g_Alo;
    const char* gBh = (const char*)g_Bhi;
    const char* gBl = (const char*)g_Blo;

    // ---- async stage loader: chunk = 32 k-values (64 B/row) ----
    auto load_stage = [&](int s, int chunk){
        uint32_t base = sb + s*STG;
        int kB = chunk*32;
        #pragma unroll
        for (int u = tid; u < 512; u += 256){       // A: 128 rows x 4 x16B
            int rowi = u >> 2, c = u & 3;
            int gr = mBase + rowi; if (gr >= S_N) gr = S_N - 1;
            size_t gb = ((size_t)gr*KDIM + kB)*2 + c*16;
            uint32_t dst = (uint32_t)(rowi*80 + c*16);
            cpa16(base + dst,          gAh + gb);
            cpa16(base + A_STG + dst,  gAl + gb);
        }
        {                                           // B: 64 rows x 4 x16B
            int u = tid;
            if (u < 256){
                int rowi = u >> 2, c = u & 3;
                size_t gb = ((size_t)(nBase + rowi)*KDIM + kB)*2 + c*16;
                uint32_t dst = (uint32_t)(rowi*80 + c*16);
                cpa16(base + 2*A_STG + dst,          gBh + gb);
                cpa16(base + 2*A_STG + B_STG + dst,  gBl + gb);
            }
        }
    };

    float acc[2][4][4];
    #pragma unroll
    for (int a = 0; a < 2; a++)
        #pragma unroll
        for (int b2 = 0; b2 < 4; b2++)
            #pragma unroll
            for (int c = 0; c < 4; c++) acc[a][b2][c] = 0.f;

    int wm = (wid & 3) * 32;    // warp m-offset within tile
    int wn = (wid >> 2) * 32;   // warp n-offset within tile

    // ldmatrix lane-address components
    uint32_t aOff = (uint32_t)((lane & 15)*80 + (lane >> 4)*16);
    uint32_t bOff = (uint32_t)(((lane & 7) + ((lane >> 4) << 3))*80 + (((lane >> 3) & 1) << 4));

    load_stage(0, 0); CPA_COMMIT();

    for (int c = 0; c < 16; c++){
        if (c < 15){ load_stage((c + 1) & 1, c + 1); CPA_COMMIT(); CPA_WAIT(1); }
        else       { CPA_WAIT(0); }
        __syncthreads();

        uint32_t base = sb + (c & 1)*STG;
        uint32_t aHiB = base + wm*80 + aOff;
        uint32_t aLoB = aHiB + A_STG;
        uint32_t bHiB = base + 2*A_STG + wn*80 + bOff;
        uint32_t bLoB = bHiB + B_STG;

        #pragma unroll
        for (int ks = 0; ks < 2; ks++){
            uint32_t ah[2][4], al[2][4], bh[8], bl[8];
            #pragma unroll
            for (int mf = 0; mf < 2; mf++){
                ldsm4(ah[mf][0], ah[mf][1], ah[mf][2], ah[mf][3],
                      aHiB + mf*16*80 + ks*32);
                ldsm4(al[mf][0], al[mf][1], al[mf][2], al[mf][3],
                      aLoB + mf*16*80 + ks*32);
            }
            #pragma unroll
            for (int p = 0; p < 2; p++){
                ldsm4(bh[p*4+0], bh[p*4+1], bh[p*4+2], bh[p*4+3],
                      bHiB + p*16*80 + ks*32);
                ldsm4(bl[p*4+0], bl[p*4+1], bl[p*4+2], bl[p*4+3],
                      bLoB + p*16*80 + ks*32);
            }
            #pragma unroll
            for (int mf = 0; mf < 2; mf++)
                #pragma unroll
                for (int nf = 0; nf < 4; nf++){
                    mma16816(acc[mf][nf], ah[mf], &bh[nf*2]);   // hi*hi
                    mma16816(acc[mf][nf], ah[mf], &bl[nf*2]);   // hi*lo
                    mma16816(acc[mf][nf], al[mf], &bh[nf*2]);   // lo*hi
                }
        }
        __syncthreads();
    }

    // ---- fused GAT epilogue on register accumulators ----
    #pragma unroll
    for (int mf = 0; mf < 2; mf++){
        #pragma unroll
        for (int half = 0; half < 2; half++){
            int row = mBase + wm + mf*16 + (lane >> 2) + half*8;
            bool ok = row < S_N;
            int rr = ok ? row : S_N - 1;
            float adv = g_ad2[rr], asv = g_as2[rr];
            float eself = lrelu(asv + adv);
            int e0 = esrc[rr*3], e1 = esrc[rr*3 + 1], e2 = esrc[rr*3 + 2];
            float v0 = lrelu(ase_s[e0] + adv);
            float v1 = lrelu(ase_s[e1] + adv);
            float v2 = lrelu(ase_s[e2] + adv);
            float mx = fmaxf(fmaxf(eself, v0), fmaxf(v1, v2));
            float aS = expf(eself - mx), a0 = expf(v0 - mx);
            float a1 = expf(v1 - mx),  a2 = expf(v2 - mx);
            float inv = 1.f / (aS + a0 + a1 + a2);
            aS *= inv; a0 *= inv; a1 *= inv; a2 *= inv;
            #pragma unroll
            for (int nf = 0; nf < 4; nf++){
                #pragma unroll
                for (int j = 0; j < 2; j++){
                    int cl = wn + nf*8 + (lane & 3)*2 + j;
                    int col = nBase + cl;
                    float v = stu[(size_t)rr*KDIM + col] + b_s[cl]
                            + aS*acc[mf][nf][half*2 + j]
                            + a0*he_s[e0][cl] + a1*he_s[e1][cl] + a2*he_s[e2][cl];
                    if (ok) out[(size_t)row*KDIM + col] = v;
                }
            }
        }
    }
}

// ---------------- launcher ----------------
extern "C" void kernel_launch(void* const* d_in, const int* in_sizes, int n_in,
                              void* d_out, int out_size){
    const float* kn   = (const float*)d_in[0];
    const float* exer = (const float*)d_in[1];
    const float* stu  = (const float*)d_in[2];
    const float* Wg   = (const float*)d_in[3];
    const float* a_s  = (const float*)d_in[4];
    const float* a_d  = (const float*)d_in[5];
    const float* bg   = (const float*)d_in[6];
    const float* aw   = (const float*)d_in[7];
    const float* ab   = (const float*)d_in[8];
    const int* eke    = (const int*)d_in[9];
    const int* eek    = (const int*)d_in[10];
    const int* eue    = (const int*)d_in[11];
    const int* eeu    = (const int*)d_in[12];
    (void)in_sizes; (void)n_in; (void)out_size;

    float* out    = (float*)d_out;
    float* out_kn = out;
    float* out_ex = out + KDIM*KDIM;
    float* out_st = out + KDIM*KDIM + EN*KDIM;

    static int s_attr_done = 0;
    if (!s_attr_done){
        cudaFuncSetAttribute(k_gemm_mma, cudaFuncAttributeMaxDynamicSharedMemorySize,
                             MMA_SMEM);
        s_attr_done = 1;
    }

    k_pre<<<32, 512>>>(Wg, a_s, a_d, exer);
    k_init<<<1, 512>>>();
    k_split_W<<<KDIM, 256>>>(Wg);
    k_split_mv<<<(S_N + 7)/8, 256>>>(stu);
    k_matvec3<<<(KDIM + 7)/8, 256>>>(kn, KDIM);

    // GAT1 -> agg1
    k_gat1<<<1, 512>>>(eek);
    k_agg1<<<8, 512>>>(eek, kn);

    // GAT3 -> agg3
    k_gat3_max<<<(NE3 + 511)/512, 512>>>(eeu, NE3);
    k_gat3_den<<<(NE3 + 511)/512, 512>>>(eeu, NE3);
    k_gat3_agg<<<(S_N + 63)/64, 256>>>(eeu, stu, S_N, NE3);

    // B, C then exer_out
    k_bc<<<12, 512>>>(Wg, bg, exer);
    k_exer<<<1, 512>>>(exer, aw, ab, out_ex);

    // kn_out (M=512): SIMT path
    {
        dim3 grid(4, 4);
        k_gemm_gat<<<grid, 256>>>(kn, Wg, bg, eke, KDIM, out_kn);
    }
    // stu_out (M=50000): HMMA tensor-core path
    {
        dim3 grid(8, (S_N + 127)/128);
        k_gemm_mma<<<grid, 256, MMA_SMEM>>>(stu, eue, bg, out_st);
    }
}